// round 17
// baseline (speedup 1.0000x reference)
#include <cuda_runtime.h>
#include <cuda_fp16.h>
#include <cstdint>

#define BB 8
#define C_IN 64
#define C_OUT 128
#define HH 256
#define WW 256
#define NK 8

#define APITCH 72            // fp16 elems per smem row (144B, conflict-free ldmatrix)
#define AROWS 396            // 6 y-blocks x 66 x-halo entries
#define WROWS 128
#define WSTAGES 3
#define CONV_THREADS 512
#define YT 8                 // y rows per split_x_pool block

__device__ float g_ppart[BB * 32 * C_IN];   // per-(b,ytile) channel sums
__device__ float g_attn[BB * NK];

// fp16 tensors: x transposed to [b][y][x][ci]; w [b][tap][co][ci]
__device__ __half g_x16[(size_t)BB * HH * WW * C_IN];
__device__ __half g_w16[(size_t)BB * 9 * C_OUT * C_IN];

// ---------------- portable tensor-core helpers (sm_80+ PTX) ----------------
__device__ __forceinline__ void ldm_x4(uint32_t& r0, uint32_t& r1, uint32_t& r2,
                                       uint32_t& r3, uint32_t addr) {
    asm volatile("ldmatrix.sync.aligned.m8n8.x4.shared.b16 {%0,%1,%2,%3}, [%4];"
                 : "=r"(r0), "=r"(r1), "=r"(r2), "=r"(r3) : "r"(addr));
}
__device__ __forceinline__ void mma_fp16(float* c, const uint32_t* a,
                                         const uint32_t* bfr) {
    asm volatile(
        "mma.sync.aligned.m16n8k16.row.col.f32.f16.f16.f32 "
        "{%0,%1,%2,%3}, {%4,%5,%6,%7}, {%8,%9}, {%0,%1,%2,%3};"
        : "+f"(c[0]), "+f"(c[1]), "+f"(c[2]), "+f"(c[3])
        : "r"(a[0]), "r"(a[1]), "r"(a[2]), "r"(a[3]), "r"(bfr[0]), "r"(bfr[1]));
}
__device__ __forceinline__ void cpasync16(uint32_t saddr, const void* g) {
    asm volatile("cp.async.cg.shared.global [%0], [%1], 16;"
                 :: "r"(saddr), "l"(g));
}
__device__ __forceinline__ void cpasync16z(uint32_t saddr, const void* g, int srcsz) {
    asm volatile("cp.async.cg.shared.global [%0], [%1], 16, %2;"
                 :: "r"(saddr), "l"(g), "r"(srcsz));
}
__device__ __forceinline__ void cp_commit() {
    asm volatile("cp.async.commit_group;");
}
__device__ __forceinline__ void cp_wait1() {
    asm volatile("cp.async.wait_group 1;");
}

// ------- Kernel 1: fused x convert/transpose + partial pooling (float4) -------
// Block = (ytile, b), 256 threads. Thread t: column quad q = t&63 (cols 4q..4q+3),
// row slice ys = t>>6 (rows ytile*8 + ys*2 .. +1). Converts to fp16 [b][y][x][ci]
// while accumulating per-channel sums; block reduces to g_ppart[b][yt][ci].
__global__ void __launch_bounds__(256) split_x_pool_kernel(const float* __restrict__ x) {
    int yt = blockIdx.x;
    int b = blockIdx.y;
    int t = threadIdx.x;
    int q = t & 63, ys = t >> 6;
    int lane = t & 31, wrp = t >> 5;
    int xc0 = q * 4;

    float s[C_IN];
    #pragma unroll
    for (int c = 0; c < C_IN; c++) s[c] = 0.f;

    for (int yy = 0; yy < 2; yy++) {
        int y = yt * YT + ys * 2 + yy;
        const float* xp = x + ((size_t)b * C_IN) * (HH * WW) + y * WW + xc0;
        size_t obase = (((size_t)b * HH + y) * WW + xc0) * C_IN;
        // channels in chunks of 8: 8 float4 loads -> 4 columns x 4 u32 -> 4 STG.128
        #pragma unroll
        for (int cc = 0; cc < 8; cc++) {
            uint32_t pk[4][4];
            #pragma unroll
            for (int p = 0; p < 4; p++) {          // channel pair within chunk
                int c = cc * 8 + p * 2;
                float4 v0 = *reinterpret_cast<const float4*>(xp + (size_t)c * (HH * WW));
                float4 v1 = *reinterpret_cast<const float4*>(xp + (size_t)(c + 1) * (HH * WW));
                s[c]     += v0.x + v0.y + v0.z + v0.w;
                s[c + 1] += v1.x + v1.y + v1.z + v1.w;
                const float* a0 = reinterpret_cast<const float*>(&v0);
                const float* a1 = reinterpret_cast<const float*>(&v1);
                #pragma unroll
                for (int j = 0; j < 4; j++) {
                    __half h0 = __float2half(a0[j]);
                    __half h1 = __float2half(a1[j]);
                    pk[j][p] = (uint32_t)__half_as_ushort(h0) |
                               ((uint32_t)__half_as_ushort(h1) << 16);
                }
            }
            #pragma unroll
            for (int j = 0; j < 4; j++) {
                uint4* dst = reinterpret_cast<uint4*>(g_x16 + obase + (size_t)j * C_IN + cc * 8);
                *dst = make_uint4(pk[j][0], pk[j][1], pk[j][2], pk[j][3]);
            }
        }
    }

    // block reduce: warp shuffle per channel, then cross-warp via smem
    __shared__ float red[8][C_IN];
    #pragma unroll
    for (int c = 0; c < C_IN; c++) {
        float v = s[c];
        #pragma unroll
        for (int o = 16; o > 0; o >>= 1) v += __shfl_xor_sync(0xFFFFFFFFu, v, o);
        if (lane == 0) red[wrp][c] = v;
    }
    __syncthreads();
    if (t < C_IN) {
        float p = 0.f;
        #pragma unroll
        for (int w2 = 0; w2 < 8; w2++) p += red[w2][t];
        g_ppart[(b * 32 + yt) * C_IN + t] = p;
    }
}

// ---------------- Kernel 2: finish pool + logits + softmax ----------------
__global__ void __launch_bounds__(512) attn_kernel(const float* __restrict__ attn_w,
                                                   const float* __restrict__ attn_b) {
    __shared__ float pooled[BB * C_IN];
    __shared__ float lg[BB * NK];
    int t = threadIdx.x;
    {
        int b = t >> 6, ci = t & 63;
        float p = 0.f;
        #pragma unroll
        for (int yt = 0; yt < 32; yt++) p += g_ppart[(b * 32 + yt) * C_IN + ci];
        pooled[t] = p * (1.0f / (HH * WW));
    }
    __syncthreads();
    if (t < BB * NK) {
        int b = t / NK, n = t % NK;
        float s = attn_b[n];
        #pragma unroll 8
        for (int c = 0; c < C_IN; c++) s += pooled[b * C_IN + c] * attn_w[n * C_IN + c];
        lg[t] = s;
    }
    __syncthreads();
    if (t < BB) {
        float m = -1e30f;
        for (int n = 0; n < NK; n++) m = fmaxf(m, lg[t * NK + n]);
        float e[NK];
        float sum = 0.f;
        for (int n = 0; n < NK; n++) { e[n] = expf(lg[t * NK + n] - m); sum += e[n]; }
        float inv = 1.0f / sum;
        for (int n = 0; n < NK; n++) g_attn[t * NK + n] = e[n] * inv;
    }
}

// ------- Kernel 3: fused mix + fp16 convert, bank read ONCE (all b per thread) ----
__global__ void mix_w_kernel(const float* __restrict__ bank) {
    int i = blockIdx.x * blockDim.x + threadIdx.x;   // over co*ci
    if (i >= C_OUT * C_IN) return;
    int ci = i & 63;
    int co = i >> 6;
    const size_t nstride = (size_t)C_OUT * C_IN * 9;
    const float* bk = bank + ((size_t)co * C_IN + ci) * 9;
    float bkr[NK][9];
    #pragma unroll
    for (int n = 0; n < NK; n++)
        #pragma unroll
        for (int tap = 0; tap < 9; tap++) bkr[n][tap] = bk[n * nstride + tap];
    #pragma unroll
    for (int b = 0; b < BB; b++) {
        float a[NK];
        #pragma unroll
        for (int n = 0; n < NK; n++) a[n] = g_attn[b * NK + n];
        #pragma unroll
        for (int tap = 0; tap < 9; tap++) {
            float s = 0.f;
            #pragma unroll
            for (int n = 0; n < NK; n++) s += a[n] * bkr[n][tap];
            g_w16[((((size_t)b * 9 + tap) * C_OUT + co) * C_IN) + ci] = __float2half(s);
        }
    }
}

// ---------------- Kernel 4: HMMA implicit-GEMM conv (pure fp16) ----------------
// CTA: 512 thr = 16 warps (4 M x 4 N). Tile M=256 pixels = 4 y-rows x 64 px,
// N=128 c_out, K = 9 taps x 64 ci, single fp16 term, fp32 accumulators.
// A staged via cp.async (group 0, zfill OOB); W per tap through a 3-STAGE
// cp.async ring -> ONE __syncthreads per tap (slot t+2 written during tap t
// was last read at tap t-1; the top-of-tap barrier orders both visibility
// and anti-overwrite). smem = 112.3KB; 1 CTA/SM, 16 warps.
__global__ void __launch_bounds__(CONV_THREADS, 1) conv_tc_kernel(float* __restrict__ out) {
    extern __shared__ __half smem[];
    __half* sA = smem;                          // [AROWS][APITCH]
    __half* sW = smem + AROWS * APITCH;         // [WSTAGES][WROWS][APITCH]

    const int tid = threadIdx.x;
    const int lane = tid & 31;
    const int wid = tid >> 5;
    const int wm = wid >> 2;          // 0..3  (local y row)
    const int wn = wid & 3;           // 0..3  (N / c_out group)
    const int x0 = blockIdx.x * 64;
    const int y0 = blockIdx.y * 4;
    const int b = blockIdx.z;

    uint32_t sA_u32 = (uint32_t)__cvta_generic_to_shared(sA);
    uint32_t sW_u32 = (uint32_t)__cvta_generic_to_shared(sW);

    // ---- stage A via cp.async (group 0): 396 rows x 8 16B chunks ----
    for (int k = tid; k < AROWS * 8; k += CONV_THREADS) {
        int row = k >> 3, sub = k & 7;
        int yblk = row / 66, xi = row - yblk * 66;
        int yy = y0 - 1 + yblk;
        int xx = x0 + xi - 1;
        bool v = (yy >= 0) && (yy < HH) && (xx >= 0) && (xx < WW);
        const __half* gsrc = g_x16 +
            (((size_t)b * HH + (v ? yy : 0)) * WW + (v ? xx : 0)) * C_IN + sub * 8;
        cpasync16z(sA_u32 + (uint32_t)(row * APITCH + sub * 8) * 2, gsrc, v ? 16 : 0);
    }
    cp_commit();   // group: A

    // ---- W prefetch plan: 1024 16B chunks per tap; 2 per thread ----
    uint32_t w_dst[2];
    const __half* w_src[2];
    #pragma unroll
    for (int s = 0; s < 2; s++) {
        int k = tid + s * CONV_THREADS;
        int row = k >> 3, sub = k & 7;
        w_dst[s] = sW_u32 + (uint32_t)(row * APITCH + sub * 8) * 2;
        w_src[s] = g_w16 + ((size_t)(b * 9 + 0) * C_OUT + row) * C_IN + sub * 8;
    }
    const size_t W_TAP_STRIDE = (size_t)C_OUT * C_IN;   // halfs per tap
    const uint32_t W_BUF_STRIDE = WROWS * APITCH * 2;   // bytes per ring slot

    auto issue_w = [&](int tap) {
        uint32_t boff = (uint32_t)(tap % WSTAGES) * W_BUF_STRIDE;
        size_t goff = (size_t)tap * W_TAP_STRIDE;
        #pragma unroll
        for (int s = 0; s < 2; s++) cpasync16(w_dst[s] + boff, w_src[s] + goff);
    };

    issue_w(0);
    cp_commit();   // group: W0
    issue_w(1);
    cp_commit();   // group: W1

    float acc[4][4][4];
    #pragma unroll
    for (int mt = 0; mt < 4; mt++)
        #pragma unroll
        for (int nt = 0; nt < 4; nt++)
            #pragma unroll
            for (int q = 0; q < 4; q++) acc[mt][nt][q] = 0.f;

    const int row16_l = lane & 15;
    const int koff_l = (lane >> 4) * 16;   // bytes

    for (int tap = 0; tap < 9; tap++) {
        cp_wait1();        // slot (tap%3) data complete (at tap0 also covers A)
        __syncthreads();   // visibility + all warps done with tap-1's slot reads

        // prefetch tap+2 into slot (tap+2)%3 (last read at tap-1; safe now)
        if (tap + 2 <= 8) issue_w(tap + 2);
        cp_commit();       // always commit to keep group counting uniform

        const int dy = tap / 3 - 1, dx = tap % 3 - 1;
        const int arow0 = (wm + dy + 1) * 66 + (dx + 1);
        const uint32_t sWb = sW_u32 + (uint32_t)(tap % WSTAGES) * W_BUF_STRIDE;

        #pragma unroll
        for (int kc = 0; kc < 4; kc++) {
            const uint32_t kb = (uint32_t)(kc * 32 + koff_l);
            uint32_t ah[4][4];
            #pragma unroll
            for (int mt = 0; mt < 4; mt++) {
                uint32_t rowoff = (uint32_t)(arow0 + 16 * mt + row16_l) * 144 + kb;
                ldm_x4(ah[mt][0], ah[mt][1], ah[mt][2], ah[mt][3], sA_u32 + rowoff);
            }
            #pragma unroll
            for (int ntp = 0; ntp < 2; ntp++) {
                uint32_t browoff = (uint32_t)(32 * wn + 16 * ntp + row16_l) * 144 + kb;
                uint32_t h0, h1, h2, h3;
                ldm_x4(h0, h1, h2, h3, sWb + browoff);
                uint32_t bh0[2] = {h0, h2}, bh1[2] = {h1, h3};
                int nt0 = 2 * ntp, nt1 = 2 * ntp + 1;
                #pragma unroll
                for (int mt = 0; mt < 4; mt++) {
                    mma_fp16(acc[mt][nt0], ah[mt], bh0);
                    mma_fp16(acc[mt][nt1], ah[mt], bh1);
                }
            }
        }
    }

    // ---- epilogue: c-frag m16n8 layout -> out[b][co][y][px] ----
    const int gid = lane >> 2, qid = lane & 3;
    const int yo = y0 + wm;
    #pragma unroll
    for (int mt = 0; mt < 4; mt++) {
        int px0 = x0 + 16 * mt + gid;
        #pragma unroll
        for (int nt = 0; nt < 4; nt++) {
            int co0 = 32 * wn + 8 * nt + 2 * qid;
            float* c = acc[mt][nt];
            size_t o00 = (((size_t)b * C_OUT + co0) * HH + yo) * WW + px0;
            size_t o01 = o00 + (size_t)HH * WW;          // co0+1
            out[o00] = c[0];
            out[o01] = c[1];
            out[o00 + 8] = c[2];                          // px0+8
            out[o01 + 8] = c[3];
        }
    }
}

extern "C" void kernel_launch(void* const* d_in, const int* in_sizes, int n_in,
                              void* d_out, int out_size) {
    const float* x    = (const float*)d_in[0];
    const float* bank = (const float*)d_in[1];
    const float* aw   = (const float*)d_in[2];
    const float* ab   = (const float*)d_in[3];
    float* out = (float*)d_out;

    split_x_pool_kernel<<<dim3(32, BB), 256>>>(x);
    attn_kernel<<<1, 512>>>(aw, ab);
    mix_w_kernel<<<(C_OUT * C_IN + 255) / 256, 256>>>(bank);

    const int smem_bytes = (AROWS + WSTAGES * WROWS) * APITCH * 2;  // 112,320 B
    cudaFuncSetAttribute(conv_tc_kernel,
                         cudaFuncAttributeMaxDynamicSharedMemorySize, smem_bytes);
    dim3 g(WW / 64, HH / 4, BB);
    conv_tc_kernel<<<g, CONV_THREADS, smem_bytes>>>(out);
}